// round 16
// baseline (speedup 1.0000x reference)
#include <cuda_runtime.h>
#include <cuda_fp16.h>
#include <cstdint>

#define Bn 8
#define Sn 1024
#define Dn 1024
#define Hn 16
#define DKn 64
#define Mn (Bn * Sn)     // 8192
#define BHn (Bn * Hn)    // 128

// ---------------------------------------------------------------------------
// Scratch (__device__ globals; allocation-free rule)
// ---------------------------------------------------------------------------
__device__ __half g_A0H[(size_t)Mn * Dn];  // query hi / later ctx hi
__device__ __half g_A1H[(size_t)Mn * Dn];  // key hi
__device__ __half g_A2H[(size_t)Mn * Dn];  // value hi
__device__ __half g_WH[4][(size_t)Dn * Dn];  // weight^T hi [n][k] x4
__device__ __half g_QH[(size_t)BHn * Sn * DKn];
__device__ __half g_KH[(size_t)BHn * Sn * DKn];
__device__ __half g_VTH[(size_t)BHn * DKn * Sn];  // [BH,DK,S]

// ---------------------------------------------------------------------------
// helpers
// ---------------------------------------------------------------------------
__device__ __forceinline__ void cp_async16(void* smem, const void* gmem) {
    uint32_t s = (uint32_t)__cvta_generic_to_shared(smem);
    asm volatile("cp.async.cg.shared.global [%0], [%1], 16;" :: "r"(s), "l"(gmem));
}
#define CP_COMMIT asm volatile("cp.async.commit_group;")
#define CP_WAIT0  asm volatile("cp.async.wait_group 0;" ::: "memory")
#define CP_WAIT1  asm volatile("cp.async.wait_group 1;" ::: "memory")

__device__ __forceinline__ void mma_f16(float c[4], const uint32_t a[4], const uint32_t b[2]) {
    asm volatile(
        "mma.sync.aligned.m16n8k16.row.col.f32.f16.f16.f32 "
        "{%0,%1,%2,%3}, {%4,%5,%6,%7}, {%8,%9}, {%0,%1,%2,%3};\n"
        : "+f"(c[0]), "+f"(c[1]), "+f"(c[2]), "+f"(c[3])
        : "r"(a[0]), "r"(a[1]), "r"(a[2]), "r"(a[3]), "r"(b[0]), "r"(b[1]));
}

__device__ __forceinline__ void ldm_x4(uint32_t d[4], uint32_t addr) {
    asm volatile("ldmatrix.sync.aligned.m8n8.x4.shared.b16 {%0,%1,%2,%3}, [%4];"
        : "=r"(d[0]), "=r"(d[1]), "=r"(d[2]), "=r"(d[3]) : "r"(addr));
}

__device__ __forceinline__ uint32_t packh2(float x, float y) {
    __half2 h = __floats2half2_rn(x, y);
    return *(uint32_t*)&h;
}

// ---------------------------------------------------------------------------
// Unified prepass (one launch):
//   z 0..2 : fp32 -> f16 convert of the 3 inputs (elementwise, float4)
//   z 3..6 : W[k][n] fp32 -> WH[z-3][n][k] f16 (transpose + convert)
// ---------------------------------------------------------------------------
__global__ void prep_all(const float* __restrict__ x0, const float* __restrict__ x1,
                         const float* __restrict__ x2,
                         const float* __restrict__ W0, const float* __restrict__ W1,
                         const float* __restrict__ W2, const float* __restrict__ W3,
                         __half* __restrict__ h0, __half* __restrict__ h1,
                         __half* __restrict__ h2, __half* __restrict__ WHp, int n4)
{
    const int z = blockIdx.y;
    if (z < 3) {
        int i = blockIdx.x * 256 + threadIdx.x;
        if (i >= n4) return;
        const float* x = z == 0 ? x0 : z == 1 ? x1 : x2;
        __half* h      = z == 0 ? h0 : z == 1 ? h1 : h2;
        float4 v = ((const float4*)x)[i];
        ((uint2*)h)[i] = make_uint2(packh2(v.x, v.y), packh2(v.z, v.w));
    } else {
        if (blockIdx.x >= 1024) return;
        __shared__ float t[32][33];
        const int w = z - 3;
        const float* W = w == 0 ? W0 : w == 1 ? W1 : w == 2 ? W2 : W3;
        __half* Th = WHp + (size_t)w * Dn * Dn;
        int n0 = (blockIdx.x & 31) * 32, k0 = (blockIdx.x >> 5) * 32;
        int tx = threadIdx.x & 31, ty = threadIdx.x >> 5;   // 32 x 8
#pragma unroll
        for (int j = 0; j < 4; j++)
            t[ty + 8 * j][tx] = W[(size_t)(k0 + ty + 8 * j) * Dn + n0 + tx];
        __syncthreads();
#pragma unroll
        for (int j = 0; j < 4; j++)
            Th[(size_t)(n0 + ty + 8 * j) * Dn + k0 + tx] =
                __float2half_rn(t[tx][ty + 8 * j]);
    }
}

// ---------------------------------------------------------------------------
// F16 GEMM body: C = ah*wh + bias
// MODE 0: fp32 out row-major; MODE 2: f16 out [BH,S,DK];
// MODE 3: f16 TRANSPOSED [BH,DK,S]. All scaled by outscale.
// NEW GEOMETRY: CTA tile 64x128 (M x N), warp tile 32x32, 8 warps, K-chunk 32,
// 3-stage cp.async pipeline, 3 CTAs/SM (24 warps) for latency hiding.
// smem stage s at s*STG words: [A(64x20w) | W(128x20w)].
// ---------------------------------------------------------------------------
#define GPW 20                        // smem word pitch (80 B)
#define AT  (64 * GPW)                // 1280 words
#define WT  (128 * GPW)               // 2560 words
#define STG (AT + WT)                 // 3840 words
#define OPITCH 132
#define OPM 68
#define GEMM_SMEM (3 * STG * 4)       // 46080 B (osm: <=34816 B fits)

template<int MODE>
__device__ __forceinline__ void gemm_body(
    const __half* __restrict__ Ah, const __half* __restrict__ Bth,
    const float* __restrict__ bias,
    float* __restrict__ Cf, __half* __restrict__ Ch,
    float outscale, uint32_t* smw)
{
    const int tid  = threadIdx.x;
    const int wid  = tid >> 5;
    const int lane = tid & 31;
    const int g    = lane >> 2;
    const int cq   = lane & 3;
    const int r8   = lane & 7;
    const int sub  = lane >> 3;
    const int wm   = (wid & 1) * 32;    // M: 2 warps x 32
    const int wn   = (wid >> 1) * 32;   // N: 4 warps x 32
    const int bm   = blockIdx.y * 64;
    const int bn   = blockIdx.x * 128;

    const uint32_t sb = (uint32_t)__cvta_generic_to_shared(smw);
    const uint32_t aoff = (uint32_t)(wm + ((sub & 1) << 3) + r8) * 80u + ((sub >> 1) << 4);
    const uint32_t boff = (uint32_t)(wn + ((sub >> 1) << 3) + r8) * 80u + ((sub & 1) << 4);

    float acc[2][4][4];
#pragma unroll
    for (int mt = 0; mt < 2; mt++)
#pragma unroll
        for (int nt = 0; nt < 4; nt++)
#pragma unroll
            for (int i = 0; i < 4; i++) acc[mt][nt][i] = 0.f;

    auto stage = [&](int kt, int s) {
        int off = s * STG;
        {   // A: 64 rows x 4 x 16B
            int r = tid >> 2, c = tid & 3;
            cp_async16(smw + off + r * GPW + c * 4,
                       Ah + (size_t)(bm + r) * Dn + kt + c * 8);
        }
#pragma unroll
        for (int i = 0; i < 2; i++) {   // W: 128 rows x 4 x 16B
            int f = tid + 256 * i;
            int r = f >> 2, c = f & 3;
            cp_async16(smw + off + AT + r * GPW + c * 4,
                       Bth + (size_t)(bn + r) * Dn + kt + c * 8);
        }
        CP_COMMIT;
    };

    const int nIter = Dn / 32;   // 32
    stage(0, 0);
    stage(32, 1);

    for (int it = 0; it < nIter; it++) {
        if (it + 1 < nIter) { CP_WAIT1; } else { CP_WAIT0; }
        __syncthreads();
        if (it + 2 < nIter) stage((it + 2) * 32, (it + 2) % 3);

        const uint32_t bo = sb + (uint32_t)((it % 3) * STG) * 4u;

#pragma unroll
        for (int ks = 0; ks < 2; ks++) {
            const uint32_t kso = ks * 32u;
            uint32_t fa[2][4], fb[2][4];
#pragma unroll
            for (int mt = 0; mt < 2; mt++)
                ldm_x4(fa[mt], bo + aoff + kso + mt * 1280u);
#pragma unroll
            for (int ntp = 0; ntp < 2; ntp++)
                ldm_x4(fb[ntp], bo + AT * 4u + boff + kso + ntp * 1280u);

#pragma unroll
            for (int mt = 0; mt < 2; mt++)
#pragma unroll
                for (int nt = 0; nt < 4; nt++)
                    mma_f16(acc[mt][nt], fa[mt], &fb[nt >> 1][(nt & 1) * 2]);
        }
    }

    // ---- Epilogue: round-trip through smem for coalesced output ----
    __syncthreads();
    float* osm = (float*)smw;   // MODE<3: [64 m][OPITCH n]; MODE 3: [128 n][OPM m]
#pragma unroll
    for (int mt = 0; mt < 2; mt++)
#pragma unroll
        for (int nt = 0; nt < 4; nt++)
#pragma unroll
            for (int i = 0; i < 4; i++) {
                int r = wm + mt * 16 + g + (i >> 1) * 8;
                int c = wn + nt * 8 + 2 * cq + (i & 1);
                if (MODE == 3) osm[c * OPM + r] = acc[mt][nt][i];
                else           osm[r * OPITCH + c] = acc[mt][nt][i];
            }
    __syncthreads();

    if (MODE == 3) {
        // V transposed out: VT[bh][dk][s], coalesced 4B stores (128B/warp)
        const int b = bm >> 10, s0 = bm & 1023;
#pragma unroll
        for (int rr = 0; rr < 16; rr++) {
            int n = wid * 16 + rr;
            int gcol = bn + n;
            int h = gcol >> 6, dk = gcol & 63;
            float bia = bias[gcol];
            float2 v = *(float2*)&osm[n * OPM + lane * 2];
            *(uint32_t*)(Ch + (((size_t)(b * Hn + h)) * DKn + dk) * Sn + s0 + lane * 2) =
                packh2(v.x + bia, v.y + bia);
        }
        return;
    }

    const int lane2 = 2 * lane;
    const float bia0 = bias[bn + lane2],      bia1 = bias[bn + lane2 + 1];
    const float bia2 = bias[bn + 64 + lane2], bia3 = bias[bn + 64 + lane2 + 1];

    if (MODE == 0) {
#pragma unroll
        for (int rr = 0; rr < 8; rr++) {
            int r = wid * 8 + rr;
            int m = bm + r;
            float2 v0 = *(float2*)&osm[r * OPITCH + lane2];
            float2 v1 = *(float2*)&osm[r * OPITCH + 64 + lane2];
            float2 o0 = make_float2((v0.x + bia0) * outscale, (v0.y + bia1) * outscale);
            float2 o1 = make_float2((v1.x + bia2) * outscale, (v1.y + bia3) * outscale);
            *(float2*)(Cf + (size_t)m * Dn + bn + lane2) = o0;
            *(float2*)(Cf + (size_t)m * Dn + bn + 64 + lane2) = o1;
        }
    } else {  // MODE 2: f16 [BH,S,DK]
        uint32_t* Chw = (uint32_t*)Ch;
        const int h0 = bn >> 6;          // two heads per 128-col block
#pragma unroll
        for (int rr = 0; rr < 8; rr++) {
            int r = wid * 8 + rr;
            int m = bm + r;
            int b = m >> 10, s = m & 1023;
            float2 v0 = *(float2*)&osm[r * OPITCH + lane2];
            float2 v1 = *(float2*)&osm[r * OPITCH + 64 + lane2];
            size_t w0 = (((size_t)(b * Hn + h0)) * Sn + s) * 32 + lane;
            size_t w1 = (((size_t)(b * Hn + h0 + 1)) * Sn + s) * 32 + lane;
            Chw[w0] = packh2((v0.x + bia0) * outscale, (v0.y + bia1) * outscale);
            Chw[w1] = packh2((v1.x + bia2) * outscale, (v1.y + bia3) * outscale);
        }
    }
}

// Merged QKV projection launch: blockIdx.z selects {Q,K,V}.
#define QSCALE (0.125f * 1.4426950408889634f)

__global__ __launch_bounds__(256, 3)
void qkv_gemm(const __half* __restrict__ A0, const __half* __restrict__ A1,
              const __half* __restrict__ A2, const __half* __restrict__ WHp,
              const float* __restrict__ bq, const float* __restrict__ bk,
              const float* __restrict__ bv,
              __half* __restrict__ QH, __half* __restrict__ KH,
              __half* __restrict__ VTH)
{
    extern __shared__ uint32_t smw[];
    const size_t WSZ = (size_t)Dn * Dn;
    const int z = blockIdx.z;
    if (z == 0)
        gemm_body<2>(A0, WHp, bq, nullptr, QH, QSCALE, smw);
    else if (z == 1)
        gemm_body<2>(A1, WHp + WSZ, bk, nullptr, KH, 1.0f, smw);
    else
        gemm_body<3>(A2, WHp + 2 * WSZ, bv, nullptr, VTH, 1.0f, smw);
}

// O projection (fp32 out)
__global__ __launch_bounds__(256, 3)
void gemm_o(const __half* __restrict__ Ah, const __half* __restrict__ Bth,
            const float* __restrict__ bias, float* __restrict__ Cf)
{
    extern __shared__ uint32_t smw[];
    gemm_body<0>(Ah, Bth, bias, Cf, nullptr, 1.0f, smw);
}

// ---------------------------------------------------------------------------
// Flash attention (causal), pure f16, log2-domain softmax. (R13 version)
// P fragments built directly in registers from the S accumulators.
// 8 warps, 128 q-rows per CTA, 64-col K/V tiles, 3-stage cp.async pipeline.
// Q pre-scaled by 0.125*log2e in projection. qt reversed for load balance.
// ---------------------------------------------------------------------------
#define FPW 36
#define FTILE (64 * FPW)               // 2304 words
#define FLASH_SMEM (6 * FTILE * 4)     // 55296 B

__global__ __launch_bounds__(256, 2)
void flash_f16(const __half* __restrict__ Qh, const __half* __restrict__ Kh,
               const __half* __restrict__ Vth, __half* __restrict__ Oh)
{
    extern __shared__ uint32_t smw[];

    const int tid  = threadIdx.x;
    const int wid  = tid >> 5;      // 0..7
    const int lane = tid & 31;
    const int g    = lane >> 2;
    const int cq   = lane & 3;
    const int r8   = lane & 7;
    const int sub  = lane >> 3;
    const int qt   = (int)gridDim.x - 1 - (int)blockIdx.x;  // heavy tiles first
    const int bh   = blockIdx.y;

    const int rbase = qt * 128 + wid * 16;   // this warp's first global q row

    const uint32_t sb = (uint32_t)__cvta_generic_to_shared(smw);
    const uint32_t kvoff = (uint32_t)(((sub >> 1) << 3) + r8) * 144u + ((sub & 1) << 4);

    // Q fragments (register-resident): 16 rows x 64 halfs
    uint32_t qfh[4][4];
    {
        const uint32_t* Qw = (const uint32_t*)Qh + ((size_t)bh * Sn + qt * 128 + wid * 16) * 32;
#pragma unroll
        for (int ks = 0; ks < 4; ks++) {
            int o0 = g * 32 + ks * 8 + cq;
            int o1 = (g + 8) * 32 + ks * 8 + cq;
            qfh[ks][0] = Qw[o0];  qfh[ks][1] = Qw[o1];
            qfh[ks][2] = Qw[o0 + 4]; qfh[ks][3] = Qw[o1 + 4];
        }
    }

    float ctxc[8][4];
#pragma unroll
    for (int nt = 0; nt < 8; nt++)
#pragma unroll
        for (int i = 0; i < 4; i++) ctxc[nt][i] = 0.f;
    float mo0 = -1e30f, mo1 = -1e30f, L0 = 0.f, L1 = 0.f;

    const __half* Kg = Kh  + (size_t)bh * Sn * DKn;
    const __half* Vg = Vth + (size_t)bh * DKn * Sn;

    auto load_tile = [&](int kb, int s) {
        int off = s * 2 * FTILE;
#pragma unroll
        for (int i = 0; i < 2; i++) {
            int f = tid + 256 * i;       // 0..511
            int r = f >> 3, c = f & 7;
            int dst = off + r * FPW + c * 4;
            cp_async16(smw + dst,         Kg + (size_t)(kb * 64 + r) * 64 + c * 8);
            cp_async16(smw + FTILE + dst, Vg + (size_t)r * Sn + kb * 64 + c * 8);
        }
        CP_COMMIT;
    };

    const int nkb = 2 * qt + 2;
    load_tile(0, 0);
    if (1 < nkb) load_tile(1, 1);

    for (int kb = 0; kb < nkb; kb++) {
        if (kb + 1 < nkb) { CP_WAIT1; } else { CP_WAIT0; }
        __syncthreads();
        if (kb + 2 < nkb) load_tile(kb + 2, (kb + 2) % 3);

        // warp-tile fully above the diagonal? skip
        if (kb * 64 > rbase + 15) continue;

        const uint32_t bufo = (uint32_t)((kb % 3) * 2 * FTILE) * 4u;

        float sc[8][4];
#pragma unroll
        for (int nt = 0; nt < 8; nt++)
#pragma unroll
            for (int i = 0; i < 4; i++) sc[nt][i] = 0.f;

        // S = qh @ kh^T   (log2-domain logits)
#pragma unroll
        for (int ks = 0; ks < 4; ks++) {
            const uint32_t kso = ks * 32u;
            uint32_t kbh[4][4];
#pragma unroll
            for (int ntp = 0; ntp < 4; ntp++)
                ldm_x4(kbh[ntp], sb + bufo + kvoff + kso + ntp * 2304u);
#pragma unroll
            for (int nt = 0; nt < 8; nt++)
                mma_f16(sc[nt], qfh[ks], &kbh[nt >> 1][(nt & 1) * 2]);
        }

        // causal mask with global indices (only near-diagonal tiles)
        if (kb * 64 + 63 > rbase) {
            int r0g = rbase + g, r1g = r0g + 8;
#pragma unroll
            for (int nt = 0; nt < 8; nt++) {
                int c0g = kb * 64 + nt * 8 + 2 * cq;
                if (c0g > r0g)     sc[nt][0] = -1e30f;
                if (c0g + 1 > r0g) sc[nt][1] = -1e30f;
                if (c0g > r1g)     sc[nt][2] = -1e30f;
                if (c0g + 1 > r1g) sc[nt][3] = -1e30f;
            }
        }

        // online softmax in log2 domain (rows split over 4 lanes: cq)
        float rmax0 = -1e30f, rmax1 = -1e30f;
#pragma unroll
        for (int nt = 0; nt < 8; nt++) {
            rmax0 = fmaxf(rmax0, fmaxf(sc[nt][0], sc[nt][1]));
            rmax1 = fmaxf(rmax1, fmaxf(sc[nt][2], sc[nt][3]));
        }
        rmax0 = fmaxf(rmax0, __shfl_xor_sync(0xffffffffu, rmax0, 1));
        rmax0 = fmaxf(rmax0, __shfl_xor_sync(0xffffffffu, rmax0, 2));
        rmax1 = fmaxf(rmax1, __shfl_xor_sync(0xffffffffu, rmax1, 1));
        rmax1 = fmaxf(rmax1, __shfl_xor_sync(0xffffffffu, rmax1, 2));
        float mn0 = fmaxf(mo0, rmax0), mn1 = fmaxf(mo1, rmax1);
        float alpha0 = exp2f(mo0 - mn0), alpha1 = exp2f(mo1 - mn1);
        mo0 = mn0; mo1 = mn1;

        // scale ctx BEFORE accumulating this tile's PV
#pragma unroll
        for (int nt = 0; nt < 8; nt++) {
            ctxc[nt][0] *= alpha0; ctxc[nt][1] *= alpha0;
            ctxc[nt][2] *= alpha1; ctxc[nt][3] *= alpha1;
        }

        // exp2 + build P fragments in registers + PV MMAs, per k-slice j
        float s0 = 0.f, s1 = 0.f;
#pragma unroll
        for (int j = 0; j < 4; j++) {
            int nt0 = 2 * j, nt1 = nt0 + 1;
            float p00 = exp2f(sc[nt0][0] - mn0);
            float p01 = exp2f(sc[nt0][1] - mn0);
            float p02 = exp2f(sc[nt0][2] - mn1);
            float p03 = exp2f(sc[nt0][3] - mn1);
            float p10 = exp2f(sc[nt1][0] - mn0);
            float p11 = exp2f(sc[nt1][1] - mn0);
            float p12 = exp2f(sc[nt1][2] - mn1);
            float p13 = exp2f(sc[nt1][3] - mn1);
            s0 += p00 + p01 + p10 + p11;
            s1 += p02 + p03 + p12 + p13;

            uint32_t pfh[4];
            pfh[0] = packh2(p00, p01);
            pfh[1] = packh2(p02, p03);
            pfh[2] = packh2(p10, p11);
            pfh[3] = packh2(p12, p13);

            uint32_t vb[4][4];
#pragma unroll
            for (int ntp = 0; ntp < 4; ntp++)
                ldm_x4(vb[ntp], sb + FTILE * 4u + bufo + kvoff + j * 32u + ntp * 2304u);
#pragma unroll
            for (int nt = 0; nt < 8; nt++)
                mma_f16(ctxc[nt], pfh, &vb[nt >> 1][(nt & 1) * 2]);
        }
        s0 += __shfl_xor_sync(0xffffffffu, s0, 1);
        s0 += __shfl_xor_sync(0xffffffffu, s0, 2);
        s1 += __shfl_xor_sync(0xffffffffu, s1, 1);
        s1 += __shfl_xor_sync(0xffffffffu, s1, 2);
        L0 = L0 * alpha0 + s0;
        L1 = L1 * alpha1 + s1;
    }

    // epilogue: normalize, write ctx [B,S,D]
    float inv0 = 1.f / L0, inv1 = 1.f / L1;
    int b = bh >> 4, h = bh & 15;
    int m0 = b * Sn + qt * 128 + wid * 16 + g;
    uint32_t* Ohw = (uint32_t*)Oh;
#pragma unroll
    for (int nt = 0; nt < 8; nt++) {
        size_t w0 = (size_t)m0 * 512 + h * 32 + nt * 4 + cq;
        size_t w1 = (size_t)(m0 + 8) * 512 + h * 32 + nt * 4 + cq;
        Ohw[w0] = packh2(ctxc[nt][0] * inv0, ctxc[nt][1] * inv0);
        Ohw[w1] = packh2(ctxc[nt][2] * inv1, ctxc[nt][3] * inv1);
    }
}

// ---------------------------------------------------------------------------
extern "C" void kernel_launch(void* const* d_in, const int* in_sizes, int n_in,
                              void* d_out, int out_size)
{
    const float* query = (const float*)d_in[0];
    const float* key_  = (const float*)d_in[1];
    const float* value = (const float*)d_in[2];
    // d_in[3] = mask (causal tril; handled analytically)
    const float* w_q = (const float*)d_in[4];
    const float* b_q = (const float*)d_in[5];
    const float* w_k = (const float*)d_in[6];
    const float* b_k = (const float*)d_in[7];
    const float* w_v = (const float*)d_in[8];
    const float* b_v = (const float*)d_in[9];
    const float* w_o = (const float*)d_in[10];
    const float* b_o = (const float*)d_in[11];

    __half *A0H, *A1H, *A2H, *WH, *QH, *KH, *VTH;
    cudaGetSymbolAddress((void**)&A0H, g_A0H);
    cudaGetSymbolAddress((void**)&A1H, g_A1H);
    cudaGetSymbolAddress((void**)&A2H, g_A2H);
    cudaGetSymbolAddress((void**)&WH, g_WH);
    cudaGetSymbolAddress((void**)&QH, g_QH);
    cudaGetSymbolAddress((void**)&KH, g_KH);
    cudaGetSymbolAddress((void**)&VTH, g_VTH);

    const size_t WSZ = (size_t)Dn * Dn;

    cudaFuncSetAttribute(qkv_gemm, cudaFuncAttributeMaxDynamicSharedMemorySize, GEMM_SMEM);
    cudaFuncSetAttribute(gemm_o,   cudaFuncAttributeMaxDynamicSharedMemorySize, GEMM_SMEM);
    cudaFuncSetAttribute(flash_f16, cudaFuncAttributeMaxDynamicSharedMemorySize, FLASH_SMEM);

    const int n4 = (Mn * Dn) / 4;

    // Unified prepass: inputs (z 0-2) + weight transposes (z 3-6)
    prep_all<<<dim3((n4 + 255) / 256, 7), 256>>>(
        query, key_, value, w_q, w_k, w_v, w_o, A0H, A1H, A2H, WH, n4);

    // Merged QKV projections (Q scaled by 0.125*log2e; V transposed out)
    qkv_gemm<<<dim3(Dn / 128, Mn / 64, 3), 256, GEMM_SMEM>>>(
        A0H, A1H, A2H, WH, b_q, b_k, b_v, QH, KH, VTH);

    // Flash attention -> ctx into A0H
    flash_f16<<<dim3(Sn / 128, BHn), 256, FLASH_SMEM>>>(QH, KH, VTH, A0H);

    // Output projection -> d_out (fp32)
    gemm_o<<<dim3(Dn / 128, Mn / 64), 256, GEMM_SMEM>>>(
        A0H, WH + 3 * WSZ, b_o, (float*)d_out);
}

// round 17
// speedup vs baseline: 1.0893x; 1.0893x over previous
#include <cuda_runtime.h>
#include <cuda_fp16.h>
#include <cstdint>

#define Bn 8
#define Sn 1024
#define Dn 1024
#define Hn 16
#define DKn 64
#define Mn (Bn * Sn)     // 8192
#define BHn (Bn * Hn)    // 128

// ---------------------------------------------------------------------------
// Scratch (__device__ globals; allocation-free rule)
// ---------------------------------------------------------------------------
__device__ __half g_A0H[(size_t)Mn * Dn];  // query hi / later ctx hi
__device__ __half g_A1H[(size_t)Mn * Dn];  // key hi
__device__ __half g_A2H[(size_t)Mn * Dn];  // value hi
__device__ __half g_WH[4][(size_t)Dn * Dn];  // weight^T hi [n][k] x4
__device__ __half g_QH[(size_t)BHn * Sn * DKn];
__device__ __half g_KH[(size_t)BHn * Sn * DKn];
__device__ __half g_VTH[(size_t)BHn * DKn * Sn];  // [BH,DK,S]

// ---------------------------------------------------------------------------
// helpers
// ---------------------------------------------------------------------------
__device__ __forceinline__ void cp_async16(void* smem, const void* gmem) {
    uint32_t s = (uint32_t)__cvta_generic_to_shared(smem);
    asm volatile("cp.async.cg.shared.global [%0], [%1], 16;" :: "r"(s), "l"(gmem));
}
#define CP_COMMIT asm volatile("cp.async.commit_group;")
#define CP_WAIT0  asm volatile("cp.async.wait_group 0;" ::: "memory")
#define CP_WAIT1  asm volatile("cp.async.wait_group 1;" ::: "memory")

__device__ __forceinline__ void mma_f16(float c[4], const uint32_t a[4], const uint32_t b[2]) {
    asm volatile(
        "mma.sync.aligned.m16n8k16.row.col.f32.f16.f16.f32 "
        "{%0,%1,%2,%3}, {%4,%5,%6,%7}, {%8,%9}, {%0,%1,%2,%3};\n"
        : "+f"(c[0]), "+f"(c[1]), "+f"(c[2]), "+f"(c[3])
        : "r"(a[0]), "r"(a[1]), "r"(a[2]), "r"(a[3]), "r"(b[0]), "r"(b[1]));
}

__device__ __forceinline__ void ldm_x4(uint32_t d[4], uint32_t addr) {
    asm volatile("ldmatrix.sync.aligned.m8n8.x4.shared.b16 {%0,%1,%2,%3}, [%4];"
        : "=r"(d[0]), "=r"(d[1]), "=r"(d[2]), "=r"(d[3]) : "r"(addr));
}

__device__ __forceinline__ uint32_t packh2(float x, float y) {
    __half2 h = __floats2half2_rn(x, y);
    return *(uint32_t*)&h;
}

// ---------------------------------------------------------------------------
// Unified prepass (one launch, packed):
//   z 0..2 : fp32 -> f16 convert of the 3 inputs (elementwise, float4)
//   z 3    : all 4 weight transposes packed into x (w = x >> 10)
// ---------------------------------------------------------------------------
__global__ void prep_all(const float* __restrict__ x0, const float* __restrict__ x1,
                         const float* __restrict__ x2,
                         const float* __restrict__ W0, const float* __restrict__ W1,
                         const float* __restrict__ W2, const float* __restrict__ W3,
                         __half* __restrict__ h0, __half* __restrict__ h1,
                         __half* __restrict__ h2, __half* __restrict__ WHp, int n4)
{
    const int z = blockIdx.y;
    if (z < 3) {
        int i = blockIdx.x * 256 + threadIdx.x;
        if (i >= n4) return;
        const float* x = z == 0 ? x0 : z == 1 ? x1 : x2;
        __half* h      = z == 0 ? h0 : z == 1 ? h1 : h2;
        float4 v = ((const float4*)x)[i];
        ((uint2*)h)[i] = make_uint2(packh2(v.x, v.y), packh2(v.z, v.w));
    } else {
        if (blockIdx.x >= 4096) return;       // 4 weights x 1024 tiles
        __shared__ float t[32][33];
        const int w = blockIdx.x >> 10;
        const int bx = blockIdx.x & 1023;
        const float* W = w == 0 ? W0 : w == 1 ? W1 : w == 2 ? W2 : W3;
        __half* Th = WHp + (size_t)w * Dn * Dn;
        int n0 = (bx & 31) * 32, k0 = (bx >> 5) * 32;
        int tx = threadIdx.x & 31, ty = threadIdx.x >> 5;   // 32 x 8
#pragma unroll
        for (int j = 0; j < 4; j++)
            t[ty + 8 * j][tx] = W[(size_t)(k0 + ty + 8 * j) * Dn + n0 + tx];
        __syncthreads();
#pragma unroll
        for (int j = 0; j < 4; j++)
            Th[(size_t)(n0 + ty + 8 * j) * Dn + k0 + tx] =
                __float2half_rn(t[tx][ty + 8 * j]);
    }
}

// ---------------------------------------------------------------------------
// F16 GEMM body: C = ah*wh + bias   (R13 geometry — measured best)
// MODE 0: fp32 out row-major; MODE 2: f16 out [BH,S,DK];
// MODE 3: f16 TRANSPOSED [BH,DK,S]. All scaled by outscale.
// Block tile 128x128, K-chunk 64 (rows of 64 halfs, 144B pitch), 8 warps
// (64x32 warp tile), 3-stage cp.async pipeline, 2 CTAs/SM.
// ---------------------------------------------------------------------------
#define GPW64 36                      // smem word pitch (144 B)
#define GT64 (128 * GPW64)            // 4608 words per tile region
#define OPITCH 132
#define GEMM_SMEM (6 * GT64 * 4)      // 110592 B (epilogue osm 67584 B fits)

template<int MODE>
__device__ __forceinline__ void gemm_body(
    const __half* __restrict__ Ah, const __half* __restrict__ Bth,
    const float* __restrict__ bias,
    float* __restrict__ Cf, __half* __restrict__ Ch,
    float outscale, uint32_t* smw)
{
    const int tid  = threadIdx.x;
    const int wid  = tid >> 5;
    const int lane = tid & 31;
    const int g    = lane >> 2;
    const int cq   = lane & 3;
    const int r8   = lane & 7;
    const int sub  = lane >> 3;
    const int wm   = (wid & 1) * 64;
    const int wn   = (wid >> 1) * 32;
    const int bm   = blockIdx.y * 128;
    const int bn   = blockIdx.x * 128;

    const uint32_t sb = (uint32_t)__cvta_generic_to_shared(smw);
    const uint32_t aoff = (uint32_t)(wm + ((sub & 1) << 3) + r8) * 144u + ((sub >> 1) << 4);
    const uint32_t boff = (uint32_t)(wn + ((sub >> 1) << 3) + r8) * 144u + ((sub & 1) << 4);

    float acc[4][4][4];
#pragma unroll
    for (int mt = 0; mt < 4; mt++)
#pragma unroll
        for (int nt = 0; nt < 4; nt++)
#pragma unroll
            for (int i = 0; i < 4; i++) acc[mt][nt][i] = 0.f;

    auto stage = [&](int kt, int s) {
        int off = s * 2 * GT64;
#pragma unroll
        for (int i = 0; i < 4; i++) {
            int f = tid + 256 * i;          // 0..1023
            int r = f >> 3, c = f & 7;      // 128 rows, 8 x 16B per row
            int dst = off + r * GPW64 + c * 4;
            cp_async16(smw + dst,        Ah  + (size_t)(bm + r) * Dn + kt + c * 8);
            cp_async16(smw + GT64 + dst, Bth + (size_t)(bn + r) * Dn + kt + c * 8);
        }
        CP_COMMIT;
    };

    const int nIter = Dn / 64;   // 16
    stage(0, 0);
    stage(64, 1);

    for (int it = 0; it < nIter; it++) {
        if (it + 1 < nIter) { CP_WAIT1; } else { CP_WAIT0; }
        __syncthreads();
        if (it + 2 < nIter) stage((it + 2) * 64, (it + 2) % 3);

        const uint32_t bo = sb + (uint32_t)((it % 3) * 2 * GT64) * 4u;

#pragma unroll
        for (int ks = 0; ks < 4; ks++) {
            const uint32_t kso = ks * 32u;
            uint32_t fah[4][4], fbh[2][4];
#pragma unroll
            for (int mt = 0; mt < 4; mt++)
                ldm_x4(fah[mt], bo + aoff + kso + mt * 2304u);
#pragma unroll
            for (int ntp = 0; ntp < 2; ntp++)
                ldm_x4(fbh[ntp], bo + GT64 * 4u + boff + kso + ntp * 2304u);

#pragma unroll
            for (int mt = 0; mt < 4; mt++)
#pragma unroll
                for (int nt = 0; nt < 4; nt++)
                    mma_f16(acc[mt][nt], fah[mt], &fbh[nt >> 1][(nt & 1) * 2]);
        }
    }

    // ---- Epilogue: round-trip through smem for coalesced output ----
    __syncthreads();
    float* osm = (float*)smw;
#pragma unroll
    for (int mt = 0; mt < 4; mt++)
#pragma unroll
        for (int nt = 0; nt < 4; nt++)
#pragma unroll
            for (int i = 0; i < 4; i++) {
                int r = wm + mt * 16 + g + (i >> 1) * 8;
                int c = wn + nt * 8 + 2 * cq + (i & 1);
                if (MODE == 3) osm[c * OPITCH + r] = acc[mt][nt][i];
                else           osm[r * OPITCH + c] = acc[mt][nt][i];
            }
    __syncthreads();

    if (MODE == 3) {
        const int b = bm >> 10, s0 = bm & 1023;
#pragma unroll
        for (int rr = 0; rr < 16; rr++) {
            int n = wid * 16 + rr;
            int gcol = bn + n;
            int h = gcol >> 6, dk = gcol & 63;
            float bia = bias[gcol];
            float4 v = *(float4*)&osm[n * OPITCH + lane * 4];
            uint2 u = make_uint2(packh2(v.x + bia, v.y + bia),
                                 packh2(v.z + bia, v.w + bia));
            *(uint2*)(Ch + (((size_t)(b * Hn + h)) * DKn + dk) * Sn + s0 + lane * 4) = u;
        }
        return;
    }

    const int lane2 = 2 * lane;
    const float bia0 = bias[bn + lane2],      bia1 = bias[bn + lane2 + 1];
    const float bia2 = bias[bn + 64 + lane2], bia3 = bias[bn + 64 + lane2 + 1];

    if (MODE == 0) {
#pragma unroll
        for (int rr = 0; rr < 16; rr++) {
            int r = wid * 16 + rr;
            int m = bm + r;
            float2 v0 = *(float2*)&osm[r * OPITCH + lane2];
            float2 v1 = *(float2*)&osm[r * OPITCH + 64 + lane2];
            float2 o0 = make_float2((v0.x + bia0) * outscale, (v0.y + bia1) * outscale);
            float2 o1 = make_float2((v1.x + bia2) * outscale, (v1.y + bia3) * outscale);
            *(float2*)(Cf + (size_t)m * Dn + bn + lane2) = o0;
            *(float2*)(Cf + (size_t)m * Dn + bn + 64 + lane2) = o1;
        }
    } else {  // MODE 2: f16 [BH,S,DK]
        uint32_t* Chw = (uint32_t*)Ch;
        const int h0 = bn >> 6;
#pragma unroll
        for (int rr = 0; rr < 16; rr++) {
            int r = wid * 16 + rr;
            int m = bm + r;
            int b = m >> 10, s = m & 1023;
            float2 v0 = *(float2*)&osm[r * OPITCH + lane2];
            float2 v1 = *(float2*)&osm[r * OPITCH + 64 + lane2];
            size_t w0 = (((size_t)(b * Hn + h0)) * Sn + s) * 32 + lane;
            size_t w1 = (((size_t)(b * Hn + h0 + 1)) * Sn + s) * 32 + lane;
            Chw[w0] = packh2((v0.x + bia0) * outscale, (v0.y + bia1) * outscale);
            Chw[w1] = packh2((v1.x + bia2) * outscale, (v1.y + bia3) * outscale);
        }
    }
}

// Merged QKV projection launch: blockIdx.z selects {Q,K,V}.
#define QSCALE (0.125f * 1.4426950408889634f)

__global__ __launch_bounds__(256, 2)
void qkv_gemm(const __half* __restrict__ A0, const __half* __restrict__ A1,
              const __half* __restrict__ A2, const __half* __restrict__ WHp,
              const float* __restrict__ bq, const float* __restrict__ bk,
              const float* __restrict__ bv,
              __half* __restrict__ QH, __half* __restrict__ KH,
              __half* __restrict__ VTH)
{
    extern __shared__ uint32_t smw[];
    const size_t WSZ = (size_t)Dn * Dn;
    const int z = blockIdx.z;
    if (z == 0)
        gemm_body<2>(A0, WHp, bq, nullptr, QH, QSCALE, smw);
    else if (z == 1)
        gemm_body<2>(A1, WHp + WSZ, bk, nullptr, KH, 1.0f, smw);
    else
        gemm_body<3>(A2, WHp + 2 * WSZ, bv, nullptr, VTH, 1.0f, smw);
}

// O projection (fp32 out)
__global__ __launch_bounds__(256, 2)
void gemm_o(const __half* __restrict__ Ah, const __half* __restrict__ Bth,
            const float* __restrict__ bias, float* __restrict__ Cf)
{
    extern __shared__ uint32_t smw[];
    gemm_body<0>(Ah, Bth, bias, Cf, nullptr, 1.0f, smw);
}

// ---------------------------------------------------------------------------
// Flash attention (causal), pure f16, log2-domain softmax. (R13 version)
// P fragments built directly in registers from the S accumulators.
// 8 warps, 128 q-rows per CTA, 64-col K/V tiles, 3-stage cp.async pipeline.
// Q pre-scaled by 0.125*log2e in projection. qt reversed for load balance.
// ---------------------------------------------------------------------------
#define FPW 36
#define FTILE (64 * FPW)               // 2304 words
#define FLASH_SMEM (6 * FTILE * 4)     // 55296 B

__global__ __launch_bounds__(256, 2)
void flash_f16(const __half* __restrict__ Qh, const __half* __restrict__ Kh,
               const __half* __restrict__ Vth, __half* __restrict__ Oh)
{
    extern __shared__ uint32_t smw[];

    const int tid  = threadIdx.x;
    const int wid  = tid >> 5;      // 0..7
    const int lane = tid & 31;
    const int g    = lane >> 2;
    const int cq   = lane & 3;
    const int r8   = lane & 7;
    const int sub  = lane >> 3;
    const int qt   = (int)gridDim.x - 1 - (int)blockIdx.x;  // heavy tiles first
    const int bh   = blockIdx.y;

    const int rbase = qt * 128 + wid * 16;   // this warp's first global q row

    const uint32_t sb = (uint32_t)__cvta_generic_to_shared(smw);
    const uint32_t kvoff = (uint32_t)(((sub >> 1) << 3) + r8) * 144u + ((sub & 1) << 4);

    // Q fragments (register-resident): 16 rows x 64 halfs
    uint32_t qfh[4][4];
    {
        const uint32_t* Qw = (const uint32_t*)Qh + ((size_t)bh * Sn + qt * 128 + wid * 16) * 32;
#pragma unroll
        for (int ks = 0; ks < 4; ks++) {
            int o0 = g * 32 + ks * 8 + cq;
            int o1 = (g + 8) * 32 + ks * 8 + cq;
            qfh[ks][0] = Qw[o0];  qfh[ks][1] = Qw[o1];
            qfh[ks][2] = Qw[o0 + 4]; qfh[ks][3] = Qw[o1 + 4];
        }
    }

    float ctxc[8][4];
#pragma unroll
    for (int nt = 0; nt < 8; nt++)
#pragma unroll
        for (int i = 0; i < 4; i++) ctxc[nt][i] = 0.f;
    float mo0 = -1e30f, mo1 = -1e30f, L0 = 0.f, L1 = 0.f;

    const __half* Kg = Kh  + (size_t)bh * Sn * DKn;
    const __half* Vg = Vth + (size_t)bh * DKn * Sn;

    auto load_tile = [&](int kb, int s) {
        int off = s * 2 * FTILE;
#pragma unroll
        for (int i = 0; i < 2; i++) {
            int f = tid + 256 * i;       // 0..511
            int r = f >> 3, c = f & 7;
            int dst = off + r * FPW + c * 4;
            cp_async16(smw + dst,         Kg + (size_t)(kb * 64 + r) * 64 + c * 8);
            cp_async16(smw + FTILE + dst, Vg + (size_t)r * Sn + kb * 64 + c * 8);
        }
        CP_COMMIT;
    };

    const int nkb = 2 * qt + 2;
    load_tile(0, 0);
    if (1 < nkb) load_tile(1, 1);

    for (int kb = 0; kb < nkb; kb++) {
        if (kb + 1 < nkb) { CP_WAIT1; } else { CP_WAIT0; }
        __syncthreads();
        if (kb + 2 < nkb) load_tile(kb + 2, (kb + 2) % 3);

        // warp-tile fully above the diagonal? skip
        if (kb * 64 > rbase + 15) continue;

        const uint32_t bufo = (uint32_t)((kb % 3) * 2 * FTILE) * 4u;

        float sc[8][4];
#pragma unroll
        for (int nt = 0; nt < 8; nt++)
#pragma unroll
            for (int i = 0; i < 4; i++) sc[nt][i] = 0.f;

        // S = qh @ kh^T   (log2-domain logits)
#pragma unroll
        for (int ks = 0; ks < 4; ks++) {
            const uint32_t kso = ks * 32u;
            uint32_t kbh[4][4];
#pragma unroll
            for (int ntp = 0; ntp < 4; ntp++)
                ldm_x4(kbh[ntp], sb + bufo + kvoff + kso + ntp * 2304u);
#pragma unroll
            for (int nt = 0; nt < 8; nt++)
                mma_f16(sc[nt], qfh[ks], &kbh[nt >> 1][(nt & 1) * 2]);
        }

        // causal mask with global indices (only near-diagonal tiles)
        if (kb * 64 + 63 > rbase) {
            int r0g = rbase + g, r1g = r0g + 8;
#pragma unroll
            for (int nt = 0; nt < 8; nt++) {
                int c0g = kb * 64 + nt * 8 + 2 * cq;
                if (c0g > r0g)     sc[nt][0] = -1e30f;
                if (c0g + 1 > r0g) sc[nt][1] = -1e30f;
                if (c0g > r1g)     sc[nt][2] = -1e30f;
                if (c0g + 1 > r1g) sc[nt][3] = -1e30f;
            }
        }

        // online softmax in log2 domain (rows split over 4 lanes: cq)
        float rmax0 = -1e30f, rmax1 = -1e30f;
#pragma unroll
        for (int nt = 0; nt < 8; nt++) {
            rmax0 = fmaxf(rmax0, fmaxf(sc[nt][0], sc[nt][1]));
            rmax1 = fmaxf(rmax1, fmaxf(sc[nt][2], sc[nt][3]));
        }
        rmax0 = fmaxf(rmax0, __shfl_xor_sync(0xffffffffu, rmax0, 1));
        rmax0 = fmaxf(rmax0, __shfl_xor_sync(0xffffffffu, rmax0, 2));
        rmax1 = fmaxf(rmax1, __shfl_xor_sync(0xffffffffu, rmax1, 1));
        rmax1 = fmaxf(rmax1, __shfl_xor_sync(0xffffffffu, rmax1, 2));
        float mn0 = fmaxf(mo0, rmax0), mn1 = fmaxf(mo1, rmax1);
        float alpha0 = exp2f(mo0 - mn0), alpha1 = exp2f(mo1 - mn1);
        mo0 = mn0; mo1 = mn1;

        // scale ctx BEFORE accumulating this tile's PV
#pragma unroll
        for (int nt = 0; nt < 8; nt++) {
            ctxc[nt][0] *= alpha0; ctxc[nt][1] *= alpha0;
            ctxc[nt][2] *= alpha1; ctxc[nt][3] *= alpha1;
        }

        // exp2 + build P fragments in registers + PV MMAs, per k-slice j
        float s0 = 0.f, s1 = 0.f;
#pragma unroll
        for (int j = 0; j < 4; j++) {
            int nt0 = 2 * j, nt1 = nt0 + 1;
            float p00 = exp2f(sc[nt0][0] - mn0);
            float p01 = exp2f(sc[nt0][1] - mn0);
            float p02 = exp2f(sc[nt0][2] - mn1);
            float p03 = exp2f(sc[nt0][3] - mn1);
            float p10 = exp2f(sc[nt1][0] - mn0);
            float p11 = exp2f(sc[nt1][1] - mn0);
            float p12 = exp2f(sc[nt1][2] - mn1);
            float p13 = exp2f(sc[nt1][3] - mn1);
            s0 += p00 + p01 + p10 + p11;
            s1 += p02 + p03 + p12 + p13;

            uint32_t pfh[4];
            pfh[0] = packh2(p00, p01);
            pfh[1] = packh2(p02, p03);
            pfh[2] = packh2(p10, p11);
            pfh[3] = packh2(p12, p13);

            uint32_t vb[4][4];
#pragma unroll
            for (int ntp = 0; ntp < 4; ntp++)
                ldm_x4(vb[ntp], sb + FTILE * 4u + bufo + kvoff + j * 32u + ntp * 2304u);
#pragma unroll
            for (int nt = 0; nt < 8; nt++)
                mma_f16(ctxc[nt], pfh, &vb[nt >> 1][(nt & 1) * 2]);
        }
        s0 += __shfl_xor_sync(0xffffffffu, s0, 1);
        s0 += __shfl_xor_sync(0xffffffffu, s0, 2);
        s1 += __shfl_xor_sync(0xffffffffu, s1, 1);
        s1 += __shfl_xor_sync(0xffffffffu, s1, 2);
        L0 = L0 * alpha0 + s0;
        L1 = L1 * alpha1 + s1;
    }

    // epilogue: normalize, write ctx [B,S,D]
    float inv0 = 1.f / L0, inv1 = 1.f / L1;
    int b = bh >> 4, h = bh & 15;
    int m0 = b * Sn + qt * 128 + wid * 16 + g;
    uint32_t* Ohw = (uint32_t*)Oh;
#pragma unroll
    for (int nt = 0; nt < 8; nt++) {
        size_t w0 = (size_t)m0 * 512 + h * 32 + nt * 4 + cq;
        size_t w1 = (size_t)(m0 + 8) * 512 + h * 32 + nt * 4 + cq;
        Ohw[w0] = packh2(ctxc[nt][0] * inv0, ctxc[nt][1] * inv0);
        Ohw[w1] = packh2(ctxc[nt][2] * inv1, ctxc[nt][3] * inv1);
    }
}

// ---------------------------------------------------------------------------
extern "C" void kernel_launch(void* const* d_in, const int* in_sizes, int n_in,
                              void* d_out, int out_size)
{
    const float* query = (const float*)d_in[0];
    const float* key_  = (const float*)d_in[1];
    const float* value = (const float*)d_in[2];
    // d_in[3] = mask (causal tril; handled analytically)
    const float* w_q = (const float*)d_in[4];
    const float* b_q = (const float*)d_in[5];
    const float* w_k = (const float*)d_in[6];
    const float* b_k = (const float*)d_in[7];
    const float* w_v = (const float*)d_in[8];
    const float* b_v = (const float*)d_in[9];
    const float* w_o = (const float*)d_in[10];
    const float* b_o = (const float*)d_in[11];

    __half *A0H, *A1H, *A2H, *WH, *QH, *KH, *VTH;
    cudaGetSymbolAddress((void**)&A0H, g_A0H);
    cudaGetSymbolAddress((void**)&A1H, g_A1H);
    cudaGetSymbolAddress((void**)&A2H, g_A2H);
    cudaGetSymbolAddress((void**)&WH, g_WH);
    cudaGetSymbolAddress((void**)&QH, g_QH);
    cudaGetSymbolAddress((void**)&KH, g_KH);
    cudaGetSymbolAddress((void**)&VTH, g_VTH);

    const size_t WSZ = (size_t)Dn * Dn;

    cudaFuncSetAttribute(qkv_gemm, cudaFuncAttributeMaxDynamicSharedMemorySize, GEMM_SMEM);
    cudaFuncSetAttribute(gemm_o,   cudaFuncAttributeMaxDynamicSharedMemorySize, GEMM_SMEM);
    cudaFuncSetAttribute(flash_f16, cudaFuncAttributeMaxDynamicSharedMemorySize, FLASH_SMEM);

    const int n4 = (Mn * Dn) / 4;

    // Unified prepass: inputs (z 0-2) + packed weight transposes (z 3)
    prep_all<<<dim3((n4 + 255) / 256, 4), 256>>>(
        query, key_, value, w_q, w_k, w_v, w_o, A0H, A1H, A2H, WH, n4);

    // Merged QKV projections (Q scaled by 0.125*log2e; V transposed out)
    qkv_gemm<<<dim3(Dn / 128, Mn / 128, 3), 256, GEMM_SMEM>>>(
        A0H, A1H, A2H, WH, b_q, b_k, b_v, QH, KH, VTH);

    // Flash attention -> ctx into A0H
    flash_f16<<<dim3(Sn / 128, BHn), 256, FLASH_SMEM>>>(QH, KH, VTH, A0H);

    // Output projection -> d_out (fp32)
    gemm_o<<<dim3(Dn / 128, Mn / 128), 256, GEMM_SMEM>>>(
        A0H, WH + 3 * WSZ, b_o, (float*)d_out);
}